// round 3
// baseline (speedup 1.0000x reference)
#include <cuda_runtime.h>
#include <math.h>
#include <float.h>

#define BATCH 2
#define NPTS  4096
#define FDIM  64
#define KNN   20
#define NROWS (BATCH*NPTS)

// Scratch (static __device__ arrays -- no allocation)
__device__ float  g_Wh[NROWS*FDIM];
__device__ float  g_f1[NROWS];
__device__ float  g_f2[NROWS];
__device__ float4 g_pos4[NROWS];

// ---------------------------------------------------------------------------
// Kernel 1: Wh = x@W ; f1 = Wh@a[:64] ; f2 = Wh@a[64:] ; pos4 = (x,y,z,|p|^2)
// 256 threads per block, 4 rows per block. tid = r*64 + f.
// ---------------------------------------------------------------------------
__global__ void __launch_bounds__(256) prep_kernel(
        const float* __restrict__ x,
        const float* __restrict__ pos,
        const float* __restrict__ W,
        const float* __restrict__ a)
{
    __shared__ float Ws[FDIM*FDIM];
    __shared__ float xs[4][FDIM];
    __shared__ float red1[8];
    __shared__ float red2[8];

    int tid = threadIdx.x;
    for (int i = tid; i < FDIM*FDIM; i += 256) Ws[i] = W[i];

    int r   = tid >> 6;            // local row 0..3
    int f   = tid & 63;            // feature
    int row = blockIdx.x * 4 + r;  // global row in [0, B*N)
    xs[r][f] = x[row*FDIM + f];
    __syncthreads();

    float acc = 0.f;
    #pragma unroll
    for (int k2 = 0; k2 < FDIM; k2++)
        acc += xs[r][k2] * Ws[k2*FDIM + f];
    g_Wh[row*FDIM + f] = acc;

    // f1/f2 partials: row spans warps 2r and 2r+1
    float c1 = acc * a[f];
    float c2 = acc * a[FDIM + f];
    #pragma unroll
    for (int off = 16; off; off >>= 1) {
        c1 += __shfl_down_sync(0xffffffffu, c1, off);
        c2 += __shfl_down_sync(0xffffffffu, c2, off);
    }
    int warp = tid >> 5;
    if ((tid & 31) == 0) { red1[warp] = c1; red2[warp] = c2; }
    __syncthreads();
    if (f == 0) {
        g_f1[row] = red1[2*r] + red1[2*r + 1];
        g_f2[row] = red2[2*r] + red2[2*r + 1];
    }

    // pack pos4 for the 4 rows of this block
    if (tid < 4) {
        int rw = blockIdx.x * 4 + tid;
        float px = pos[rw*3 + 0], py = pos[rw*3 + 1], pz = pos[rw*3 + 2];
        g_pos4[rw] = make_float4(px, py, pz, px*px + py*py + pz*pz);
    }
}

// ---------------------------------------------------------------------------
// Kernel 2: fused KNN(21, drop self) + edge softmax + aggregation + pos MLP
// One block (256 threads) per query node. d2 candidates live in registers
// (16 per thread). 21 rounds of block argmin with top_k tie semantics.
// ---------------------------------------------------------------------------
__global__ void __launch_bounds__(256) gat_kernel(
        const float* __restrict__ Wp,
        const float* __restrict__ bp,
        float* __restrict__ out)
{
    __shared__ float red_v[8];
    __shared__ int   red_i[8];
    __shared__ int   nbr[KNN + 1];
    __shared__ float attn[KNN];

    int tid  = threadIdx.x;
    int lane = tid & 31;
    int warp = tid >> 5;

    int q = blockIdx.x;          // flattened b*N + n
    int b = q >> 12;             // N = 4096
    const float4* posb = g_pos4 + (b << 12);
    float4 qp = g_pos4[q];       // broadcast load

    // ---- Phase 1: d2 for 4096 candidates, 16 per thread, in registers ----
    float d2r[16];
    #pragma unroll
    for (int s = 0; s < 16; s++) {
        float4 p = posb[s*256 + tid];
        float dot = qp.x*p.x + qp.y*p.y + qp.z*p.z;
        d2r[s] = (qp.w + p.w) - 2.0f*dot;   // sq[n] + sq[m] - 2*dot
    }
    // cached local argmin (slot s -> global index m = s*256 + tid)
    float lv = d2r[0]; int ls = 0;
    #pragma unroll
    for (int s = 1; s < 16; s++) if (d2r[s] < lv) { lv = d2r[s]; ls = s; }

    // ---- Phase 2: 21 rounds of block argmin (ties -> lowest index) ----
    for (int r = 0; r < KNN + 1; r++) {
        float v  = lv;
        int   mi = (ls << 8) | tid;   // = ls*256 + tid = global m
        #pragma unroll
        for (int off = 16; off; off >>= 1) {
            float ov = __shfl_down_sync(0xffffffffu, v,  off);
            int   oi = __shfl_down_sync(0xffffffffu, mi, off);
            if (ov < v || (ov == v && oi < mi)) { v = ov; mi = oi; }
        }
        if (lane == 0) { red_v[warp] = v; red_i[warp] = mi; }
        __syncthreads();
        float bv = red_v[0]; int bi = red_i[0];
        #pragma unroll
        for (int w = 1; w < 8; w++) {
            float wv = red_v[w]; int wi = red_i[w];
            if (wv < bv || (wv == bv && wi < bi)) { bv = wv; bi = wi; }
        }
        if (tid == 0) nbr[r] = bi;
        if ((bi & 255) == tid) {          // owner invalidates + rescans
            int slot = bi >> 8;
            #pragma unroll
            for (int s = 0; s < 16; s++) if (s == slot) d2r[s] = FLT_MAX;
            lv = d2r[0]; ls = 0;
            #pragma unroll
            for (int s = 1; s < 16; s++) if (d2r[s] < lv) { lv = d2r[s]; ls = s; }
        }
        __syncthreads();
    }

    // ---- Phase 3: edge scores + softmax over the 20 neighbors (warp 0) ----
    if (warp == 0) {
        float e = -FLT_MAX;
        if (lane >= 1 && lane < KNN + 1) {
            int m = nbr[lane];
            e = g_f1[q] + g_f2[(b << 12) + m];
            e = (e > 0.f) ? e : 0.2f * e;           // leaky relu
        }
        float mx = e;
        #pragma unroll
        for (int off = 16; off; off >>= 1)
            mx = fmaxf(mx, __shfl_xor_sync(0xffffffffu, mx, off));
        float p = (lane >= 1 && lane < KNN + 1) ? expf(e - mx) : 0.f;
        float sm = p;
        #pragma unroll
        for (int off = 16; off; off >>= 1)
            sm += __shfl_xor_sync(0xffffffffu, sm, off);
        if (lane >= 1 && lane < KNN + 1) attn[lane - 1] = p / sm;
    }
    __syncthreads();

    // ---- Phase 4: h = attn @ Wh[nbr] + relu(pos@Wp + bp); elu ----
    if (tid < FDIM) {
        const float* whb = g_Wh + ((size_t)(b << 12)) * FDIM;
        float acc = 0.f;
        #pragma unroll
        for (int j = 0; j < KNN; j++)
            acc += attn[j] * whb[nbr[j + 1] * FDIM + tid];
        float pf = qp.x*Wp[tid] + qp.y*Wp[FDIM + tid] + qp.z*Wp[2*FDIM + tid] + bp[tid];
        pf = fmaxf(pf, 0.f);
        float h = acc + pf;
        out[(size_t)q * FDIM + tid] = (h > 0.f) ? h : expm1f(h);
    }
}

// ---------------------------------------------------------------------------
extern "C" void kernel_launch(void* const* d_in, const int* in_sizes, int n_in,
                              void* d_out, int out_size)
{
    const float* x   = (const float*)d_in[0];
    const float* pos = (const float*)d_in[1];
    const float* W   = (const float*)d_in[2];
    const float* a   = (const float*)d_in[3];
    const float* Wp  = (const float*)d_in[4];
    const float* bp  = (const float*)d_in[5];
    // d_in[6] is k (=20), compiled in.

    prep_kernel<<<NROWS / 4, 256>>>(x, pos, W, a);
    gat_kernel<<<NROWS, 256>>>(Wp, bp, (float*)d_out);
}

// round 6
// speedup vs baseline: 1.6108x; 1.6108x over previous
#include <cuda_runtime.h>
#include <math.h>
#include <float.h>

#define BATCH 2
#define NPTS  4096
#define FDIM  64
#define KNN   20
#define NROWS (BATCH*NPTS)

// Scratch (static __device__ arrays -- no allocation)
__device__ float  g_Wh[NROWS*FDIM];
__device__ float  g_f1[NROWS];
__device__ float  g_f2[NROWS];
__device__ float4 g_pos4[NROWS];

// ---------------------------------------------------------------------------
// Kernel 1: Wh = x@W ; f1 = Wh@a[:64] ; f2 = Wh@a[64:] ; pos4 = (x,y,z,|p|^2)
// ---------------------------------------------------------------------------
__global__ void __launch_bounds__(256) prep_kernel(
        const float* __restrict__ x,
        const float* __restrict__ pos,
        const float* __restrict__ W,
        const float* __restrict__ a)
{
    __shared__ float Ws[FDIM*FDIM];
    __shared__ float xs[4][FDIM];
    __shared__ float red1[8];
    __shared__ float red2[8];

    int tid = threadIdx.x;
    for (int i = tid; i < FDIM*FDIM; i += 256) Ws[i] = W[i];

    int r   = tid >> 6;            // local row 0..3
    int f   = tid & 63;            // feature
    int row = blockIdx.x * 4 + r;  // global row in [0, B*N)
    xs[r][f] = x[row*FDIM + f];
    __syncthreads();

    float acc = 0.f;
    #pragma unroll
    for (int k2 = 0; k2 < FDIM; k2++)
        acc += xs[r][k2] * Ws[k2*FDIM + f];
    g_Wh[row*FDIM + f] = acc;

    float c1 = acc * a[f];
    float c2 = acc * a[FDIM + f];
    #pragma unroll
    for (int off = 16; off; off >>= 1) {
        c1 += __shfl_down_sync(0xffffffffu, c1, off);
        c2 += __shfl_down_sync(0xffffffffu, c2, off);
    }
    int warp = tid >> 5;
    if ((tid & 31) == 0) { red1[warp] = c1; red2[warp] = c2; }
    __syncthreads();
    if (f == 0) {
        g_f1[row] = red1[2*r] + red1[2*r + 1];
        g_f2[row] = red2[2*r] + red2[2*r + 1];
    }

    if (tid < 4) {
        int rw = blockIdx.x * 4 + tid;
        float px = pos[rw*3 + 0], py = pos[rw*3 + 1], pz = pos[rw*3 + 2];
        g_pos4[rw] = make_float4(px, py, pz, px*px + py*py + pz*pz);
    }
}

// ---------------------------------------------------------------------------
// Monotonic 64-bit key: upper 32 bits = order-preserving f32 bits, low 12 =
// candidate index. min(key) == (min d2, ties -> lowest index) == top_k order.
// ---------------------------------------------------------------------------
__device__ __forceinline__ unsigned long long pack_key(float v, int m) {
    unsigned u = __float_as_uint(v);
    u = u ^ ((unsigned)((int)u >> 31) | 0x80000000u);
    return ((unsigned long long)u << 12) | (unsigned)m;
}

__device__ __forceinline__ unsigned long long warp_min_key(unsigned long long k) {
    #pragma unroll
    for (int off = 16; off; off >>= 1) {
        unsigned long long o = __shfl_xor_sync(0xffffffffu, k, off);
        if (o < k) k = o;
    }
    return k;   // all lanes hold the warp min
}

// ---------------------------------------------------------------------------
// Kernel 2: fused KNN(21, drop self) + edge softmax + aggregation + pos MLP
// One 256-thread block per query. d2 candidates in registers (16/thread).
// Cached tournament: per round only warp 0 (merge of 8 cached warp-mins) and
// the owner warp (rescan + re-tree) do work.
// ---------------------------------------------------------------------------
__global__ void __launch_bounds__(256) gat_kernel(
        const float* __restrict__ Wp,
        const float* __restrict__ bp,
        float* __restrict__ out)
{
    __shared__ unsigned long long wmin[8];     // cached per-warp min key
    __shared__ unsigned long long winkey_s;
    __shared__ int   owner_s;
    __shared__ int   nbr[KNN + 1];
    __shared__ float attn[KNN];

    int tid  = threadIdx.x;
    int lane = tid & 31;
    int warp = tid >> 5;

    int q = blockIdx.x;          // flattened b*N + n
    int b = q >> 12;             // N = 4096
    const float4* posb = g_pos4 + (b << 12);
    float4 qp = g_pos4[q];

    // ---- Phase 1: d2 for 4096 candidates, 16 per thread, in registers ----
    float d2r[16];
    #pragma unroll
    for (int s = 0; s < 16; s++) {
        float4 p = posb[s*256 + tid];
        float dot = qp.x*p.x + qp.y*p.y + qp.z*p.z;
        d2r[s] = (qp.w + p.w) - 2.0f*dot;       // sq[n] + sq[m] - 2*dot
    }
    // local argmin (strict <, ascending slot => lowest index on value ties)
    float lv = d2r[0]; int ls = 0;
    #pragma unroll
    for (int s = 1; s < 16; s++) if (d2r[s] < lv) { lv = d2r[s]; ls = s; }
    unsigned long long lkey = pack_key(lv, (ls << 8) | tid);

    // initial per-warp trees
    {
        unsigned long long wk = warp_min_key(lkey);
        if (lane == 0) wmin[warp] = wk;
    }
    __syncthreads();

    // ---- Phase 2: 21 rounds, cached tournament ----
    for (int r = 0; r < KNN + 1; r++) {
        if (warp == 0) {
            unsigned long long orig = (lane < 8) ? wmin[lane] : ~0ULL;
            unsigned long long m = orig;
            #pragma unroll
            for (int off = 4; off; off >>= 1) {
                unsigned long long o = __shfl_xor_sync(0xffffffffu, m, off);
                if (o < m) m = o;
            }
            unsigned bal = __ballot_sync(0xffffffffu, (orig == m) && (lane < 8));
            if (lane == 0) {
                owner_s  = __ffs(bal) - 1;
                winkey_s = m;
                nbr[r]   = (int)(m & 0xFFFu);
            }
        }
        __syncthreads();
        if (warp == owner_s) {
            unsigned long long wkey = winkey_s;
            if (lkey == wkey) {                       // unique owner thread
                int slot = (int)((wkey >> 8) & 15u);
                #pragma unroll
                for (int s = 0; s < 16; s++) if (s == slot) d2r[s] = FLT_MAX;
                lv = d2r[0]; ls = 0;
                #pragma unroll
                for (int s = 1; s < 16; s++) if (d2r[s] < lv) { lv = d2r[s]; ls = s; }
                lkey = pack_key(lv, (ls << 8) | tid);
            }
            unsigned long long wk = warp_min_key(lkey);
            if (lane == 0) wmin[warp] = wk;
        }
        __syncthreads();
    }

    // ---- Phase 3: edge scores + softmax over the 20 neighbors (warp 0) ----
    if (warp == 0) {
        float e = -FLT_MAX;
        if (lane >= 1 && lane < KNN + 1) {
            int m = nbr[lane];
            e = g_f1[q] + g_f2[(b << 12) + m];
            e = (e > 0.f) ? e : 0.2f * e;             // leaky relu
        }
        float mx = e;
        #pragma unroll
        for (int off = 16; off; off >>= 1)
            mx = fmaxf(mx, __shfl_xor_sync(0xffffffffu, mx, off));
        float p = (lane >= 1 && lane < KNN + 1) ? expf(e - mx) : 0.f;
        float sm = p;
        #pragma unroll
        for (int off = 16; off; off >>= 1)
            sm += __shfl_xor_sync(0xffffffffu, sm, off);
        if (lane >= 1 && lane < KNN + 1) attn[lane - 1] = p / sm;
    }
    __syncthreads();

    // ---- Phase 4: h = attn @ Wh[nbr] + relu(pos@Wp + bp); elu ----
    if (tid < FDIM) {
        const float* whb = g_Wh + ((size_t)(b << 12)) * FDIM;
        float acc = 0.f;
        #pragma unroll
        for (int j = 0; j < KNN; j++)
            acc += attn[j] * whb[nbr[j + 1] * FDIM + tid];
        float pf = qp.x*Wp[tid] + qp.y*Wp[FDIM + tid] + qp.z*Wp[2*FDIM + tid] + bp[tid];
        pf = fmaxf(pf, 0.f);
        float h = acc + pf;
        out[(size_t)q * FDIM + tid] = (h > 0.f) ? h : expm1f(h);
    }
}

// ---------------------------------------------------------------------------
extern "C" void kernel_launch(void* const* d_in, const int* in_sizes, int n_in,
                              void* d_out, int out_size)
{
    const float* x   = (const float*)d_in[0];
    const float* pos = (const float*)d_in[1];
    const float* W   = (const float*)d_in[2];
    const float* a   = (const float*)d_in[3];
    const float* Wp  = (const float*)d_in[4];
    const float* bp  = (const float*)d_in[5];
    // d_in[6] is k (=20), compiled in.

    prep_kernel<<<NROWS / 4, 256>>>(x, pos, W, a);
    gat_kernel<<<NROWS, 256>>>(Wp, bp, (float*)d_out);
}